// round 2
// baseline (speedup 1.0000x reference)
#include <cuda_runtime.h>
#include <cstddef>

#define BATCH 1024
#define SEQL  50
#define DIM   4
#define HID   512
#define TLEN  30

// ---------------- scratch (device globals: no allocation allowed) ----------
__device__ float g_enc[(size_t)BATCH * SEQL * HID];   // encoder outputs (B, L, H)
__device__ float g_hbuf[2 * BATCH * HID];             // ping-pong h
__device__ float g_c[BATCH * HID];                    // c (in-place safe)
__device__ float g_attn[BATCH * HID];                 // attn_applied
__device__ float g_comb[BATCH * HID];                 // comb (relu output)
__device__ float g_x[BATCH * DIM];                    // decoder input carry

__device__ __forceinline__ float sigf(float x) { return 1.0f / (1.0f + expf(-x)); }

// ---------------- init: h0 = c0 = 0, x0 = input[:, L-1, :] -----------------
__global__ void init_kernel(const float* __restrict__ input, float* __restrict__ h0,
                            float* __restrict__ c0, float* __restrict__ x0) {
    int i = blockIdx.x * blockDim.x + threadIdx.x;
    if (i < BATCH * HID) { h0[i] = 0.0f; c0[i] = 0.0f; }
    if (i < BATCH * DIM) {
        int b = i >> 2, d = i & 3;
        x0[i] = input[(size_t)b * SEQL * DIM + (size_t)(SEQL - 1) * DIM + d];
    }
}

// ---------------- fused LSTM cell ------------------------------------------
// gates[b][g*H+j] = inp@W_ih^T + h@W_hh^T + b_ih + b_hh, then LSTM update.
// Tile: 64 batch x 64 hidden x 4 gates, 256 threads, K-tiles of 32.
// BIG_IN=0: inp is (B, stride) with Din=4 (encoder, fused directly)
// BIG_IN=1: inp is (B, 512) dense (decoder: comb), second GEMM pass.
template <int BIG_IN>
__global__ void lstm_cell_kernel(
    const float* __restrict__ inp, int inp_stride,
    const float* __restrict__ h_in,
    const float* __restrict__ W_ih, const float* __restrict__ W_hh,
    const float* __restrict__ b_ih, const float* __restrict__ b_hh,
    float* __restrict__ h_out, float* __restrict__ c,
    float* __restrict__ enc_out /* may be null; pre-offset by t*H; per-b stride L*H */) {
    __shared__ float As[32 * 65];    // [k][b_local], pad 65 -> conflict-free
    __shared__ float Bs[32 * 257];   // [k][n], n = gate*64 + j_local, pad 257

    const int tid = threadIdx.x;
    const int tx = tid & 15;         // j-group
    const int ty = tid >> 4;         // b-group
    const int bblock = blockIdx.x * 64;
    const int jblock = blockIdx.y * 64;

    float acc[4][16];                // [ib][g*4+ij]
#pragma unroll
    for (int ib = 0; ib < 4; ib++)
#pragma unroll
        for (int n4 = 0; n4 < 16; n4++) acc[ib][n4] = 0.0f;

    const int npass = BIG_IN ? 2 : 1;
    for (int pass = 0; pass < npass; pass++) {
        const float* A = pass ? inp : h_in;
        const float* W = pass ? W_ih : W_hh;
        for (int kt = 0; kt < HID; kt += 32) {
#pragma unroll
            for (int i = 0; i < 8; i++) {
                int idx = tid + i * 256;
                int kk = idx & 31, bb = idx >> 5;
                As[kk * 65 + bb] = A[(size_t)(bblock + bb) * HID + kt + kk];
            }
#pragma unroll
            for (int i = 0; i < 32; i++) {
                int idx = tid + i * 256;
                int kk = idx & 31, nn = idx >> 5;
                int row = (nn >> 6) * HID + jblock + (nn & 63);
                Bs[kk * 257 + nn] = W[(size_t)row * HID + kt + kk];
            }
            __syncthreads();
#pragma unroll 4
            for (int kk = 0; kk < 32; kk++) {
                float a[4];
#pragma unroll
                for (int ib = 0; ib < 4; ib++) a[ib] = As[kk * 65 + ty + 16 * ib];
#pragma unroll
                for (int n4 = 0; n4 < 16; n4++) {
                    int g = n4 >> 2, ij = n4 & 3;
                    float bv = Bs[kk * 257 + g * 64 + tx + 16 * ij];
#pragma unroll
                    for (int ib = 0; ib < 4; ib++) acc[ib][n4] += a[ib] * bv;
                }
            }
            __syncthreads();
        }
    }

    if (!BIG_IN) {
        // Din = 4 input projection, done directly (W_ih is 2048x4, L1-resident)
        float xv[4][4];
#pragma unroll
        for (int ib = 0; ib < 4; ib++) {
            int bg = bblock + ty + 16 * ib;
#pragma unroll
            for (int k = 0; k < 4; k++) xv[ib][k] = inp[(size_t)bg * inp_stride + k];
        }
#pragma unroll
        for (int n4 = 0; n4 < 16; n4++) {
            int g = n4 >> 2, jl = tx + 16 * (n4 & 3);
            const float* wr = W_ih + (size_t)(g * HID + jblock + jl) * 4;
            float w0 = wr[0], w1 = wr[1], w2 = wr[2], w3 = wr[3];
#pragma unroll
            for (int ib = 0; ib < 4; ib++)
                acc[ib][n4] += xv[ib][0] * w0 + xv[ib][1] * w1 + xv[ib][2] * w2 + xv[ib][3] * w3;
        }
    }

    // epilogue: LSTM nonlinearity
#pragma unroll
    for (int ib = 0; ib < 4; ib++) {
        int bg = bblock + ty + 16 * ib;
#pragma unroll
        for (int ij = 0; ij < 4; ij++) {
            int jg = jblock + tx + 16 * ij;
            float gi = acc[ib][0 * 4 + ij] + b_ih[jg] + b_hh[jg];
            float gf = acc[ib][1 * 4 + ij] + b_ih[HID + jg] + b_hh[HID + jg];
            float gg = acc[ib][2 * 4 + ij] + b_ih[2 * HID + jg] + b_hh[2 * HID + jg];
            float go = acc[ib][3 * 4 + ij] + b_ih[3 * HID + jg] + b_hh[3 * HID + jg];
            size_t o = (size_t)bg * HID + jg;
            float cn = sigf(gf) * c[o] + sigf(gi) * tanhf(gg);
            float hn = sigf(go) * tanhf(cn);
            c[o] = cn;
            h_out[o] = hn;
            if (enc_out) enc_out[(size_t)bg * (SEQL * HID) + jg] = hn;
        }
    }
}

// ---------------- attention ------------------------------------------------
// One block per batch row. Replicates the reference's h_r scramble exactly:
// h_r[b][j] = h_flat[j*B + b] -> h[2j + (b>>9)][b & 511]  (B = 2H)
__global__ void attn_kernel(const float* __restrict__ x, const float* __restrict__ h,
                            const float* __restrict__ attn_W, const float* __restrict__ attn_b,
                            const float* __restrict__ enc, float* __restrict__ attn_out) {
    __shared__ float hr[HID];
    __shared__ float w[SEQL];
    __shared__ float red[2];

    const int b = blockIdx.x;
    const int tid = threadIdx.x;
    const int bo = b >> 9;
    const int bc = b & (HID - 1);

    for (int j = tid; j < HID; j += 256)
        hr[j] = h[(size_t)(2 * j + bo) * HID + bc];
    __syncthreads();

    const int wid = tid >> 5, lane = tid & 31;
    for (int l = wid; l < SEQL; l += 8) {
        const float* wr = attn_W + (size_t)l * (HID + DIM);
        float s = 0.0f;
        for (int j = lane; j < HID; j += 32) s += hr[j] * wr[DIM + j];
#pragma unroll
        for (int off = 16; off; off >>= 1) s += __shfl_xor_sync(0xffffffffu, s, off);
        if (lane == 0) {
            s += attn_b[l] + x[b * DIM + 0] * wr[0] + x[b * DIM + 1] * wr[1] +
                 x[b * DIM + 2] * wr[2] + x[b * DIM + 3] * wr[3];
            w[l] = s;
        }
    }
    __syncthreads();
    if (tid == 0) {
        float m = w[0];
        for (int l = 1; l < SEQL; l++) m = fmaxf(m, w[l]);
        red[0] = m;
    }
    __syncthreads();
    if (tid < SEQL) w[tid] = expf(w[tid] - red[0]);
    __syncthreads();
    if (tid == 0) {
        float s = 0.0f;
        for (int l = 0; l < SEQL; l++) s += w[l];
        red[1] = 1.0f / s;
    }
    __syncthreads();
    if (tid < SEQL) w[tid] *= red[1];
    __syncthreads();

    for (int hc = tid; hc < HID; hc += 256) {
        const float* e = enc + (size_t)b * SEQL * HID + hc;
        float acc = 0.0f;
#pragma unroll
        for (int l = 0; l < SEQL; l++) acc += w[l] * e[(size_t)l * HID];
        attn_out[(size_t)b * HID + hc] = acc;
    }
}

// ---------------- comb GEMM + relu -----------------------------------------
__global__ void comb_kernel(const float* __restrict__ x, const float* __restrict__ attn,
                            const float* __restrict__ comb_W, const float* __restrict__ comb_b,
                            float* __restrict__ out) {
    __shared__ float As[32 * 65];
    __shared__ float Bs[32 * 65];
    const int tid = threadIdx.x;
    const int tx = tid & 15, ty = tid >> 4;
    const int bblock = blockIdx.x * 64;
    const int jblock = blockIdx.y * 64;

    float acc[4][4];
#pragma unroll
    for (int ib = 0; ib < 4; ib++)
#pragma unroll
        for (int ij = 0; ij < 4; ij++) acc[ib][ij] = 0.0f;

    for (int kt = 0; kt < HID; kt += 32) {
#pragma unroll
        for (int i = 0; i < 8; i++) {
            int idx = tid + i * 256;
            int kk = idx & 31, rr = idx >> 5;
            As[kk * 65 + rr] = attn[(size_t)(bblock + rr) * HID + kt + kk];
            Bs[kk * 65 + rr] = comb_W[(size_t)(jblock + rr) * (HID + DIM) + DIM + kt + kk];
        }
        __syncthreads();
#pragma unroll 8
        for (int kk = 0; kk < 32; kk++) {
            float a[4], bw[4];
#pragma unroll
            for (int ib = 0; ib < 4; ib++) a[ib] = As[kk * 65 + ty + 16 * ib];
#pragma unroll
            for (int ij = 0; ij < 4; ij++) bw[ij] = Bs[kk * 65 + tx + 16 * ij];
#pragma unroll
            for (int ib = 0; ib < 4; ib++)
#pragma unroll
                for (int ij = 0; ij < 4; ij++) acc[ib][ij] += a[ib] * bw[ij];
        }
        __syncthreads();
    }

#pragma unroll
    for (int ib = 0; ib < 4; ib++) {
        int bg = bblock + ty + 16 * ib;
        float x0 = x[bg * DIM + 0], x1 = x[bg * DIM + 1];
        float x2 = x[bg * DIM + 2], x3 = x[bg * DIM + 3];
#pragma unroll
        for (int ij = 0; ij < 4; ij++) {
            int jg = jblock + tx + 16 * ij;
            const float* wr = comb_W + (size_t)jg * (HID + DIM);
            float v = acc[ib][ij] + comb_b[jg] + x0 * wr[0] + x1 * wr[1] + x2 * wr[2] + x3 * wr[3];
            out[(size_t)bg * HID + jg] = fmaxf(v, 0.0f);
        }
    }
}

// ---------------- pred: h @ out_W^T + out_b; writes output + next x --------
__global__ void pred_kernel(const float* __restrict__ h, const float* __restrict__ out_W,
                            const float* __restrict__ out_b, float* __restrict__ x_next,
                            float* __restrict__ out, int t) {
    const int wid = threadIdx.x >> 5, lane = threadIdx.x & 31;
    const int b = blockIdx.x * 8 + wid;
    float a0 = 0.f, a1 = 0.f, a2 = 0.f, a3 = 0.f;
    for (int j = lane; j < HID; j += 32) {
        float hv = h[(size_t)b * HID + j];
        a0 += hv * out_W[0 * HID + j];
        a1 += hv * out_W[1 * HID + j];
        a2 += hv * out_W[2 * HID + j];
        a3 += hv * out_W[3 * HID + j];
    }
#pragma unroll
    for (int off = 16; off; off >>= 1) {
        a0 += __shfl_xor_sync(0xffffffffu, a0, off);
        a1 += __shfl_xor_sync(0xffffffffu, a1, off);
        a2 += __shfl_xor_sync(0xffffffffu, a2, off);
        a3 += __shfl_xor_sync(0xffffffffu, a3, off);
    }
    if (lane == 0) {
        float v0 = a0 + out_b[0], v1 = a1 + out_b[1], v2 = a2 + out_b[2], v3 = a3 + out_b[3];
        size_t o = ((size_t)b * TLEN + t) * DIM;
        out[o + 0] = v0; out[o + 1] = v1; out[o + 2] = v2; out[o + 3] = v3;
        x_next[b * DIM + 0] = v0; x_next[b * DIM + 1] = v1;
        x_next[b * DIM + 2] = v2; x_next[b * DIM + 3] = v3;
    }
}

// ---------------- host -----------------------------------------------------
extern "C" void kernel_launch(void* const* d_in, const int* in_sizes, int n_in,
                              void* d_out, int out_size) {
    // metadata order: input_tensor, [target_len], enc_W_ih, enc_W_hh, enc_b_ih,
    // enc_b_hh, attn_W, attn_b, comb_W, comb_b, dec_W_ih, dec_W_hh, dec_b_ih,
    // dec_b_hh, out_W, out_b
    int base = 1;
    if (n_in >= 16 && in_sizes[1] == 1) base = 2;  // skip target_len scalar

    const float* input    = (const float*)d_in[0];
    const float* enc_W_ih = (const float*)d_in[base + 0];
    const float* enc_W_hh = (const float*)d_in[base + 1];
    const float* enc_b_ih = (const float*)d_in[base + 2];
    const float* enc_b_hh = (const float*)d_in[base + 3];
    const float* attn_W   = (const float*)d_in[base + 4];
    const float* attn_b   = (const float*)d_in[base + 5];
    const float* comb_W   = (const float*)d_in[base + 6];
    const float* comb_b   = (const float*)d_in[base + 7];
    const float* dec_W_ih = (const float*)d_in[base + 8];
    const float* dec_W_hh = (const float*)d_in[base + 9];
    const float* dec_b_ih = (const float*)d_in[base + 10];
    const float* dec_b_hh = (const float*)d_in[base + 11];
    const float* out_W    = (const float*)d_in[base + 12];
    const float* out_b    = (const float*)d_in[base + 13];
    float* out = (float*)d_out;

    float *enc_p, *h_p, *c_p, *attn_p, *comb_p, *x_p;
    cudaGetSymbolAddress((void**)&enc_p, g_enc);
    cudaGetSymbolAddress((void**)&h_p, g_hbuf);
    cudaGetSymbolAddress((void**)&c_p, g_c);
    cudaGetSymbolAddress((void**)&attn_p, g_attn);
    cudaGetSymbolAddress((void**)&comb_p, g_comb);
    cudaGetSymbolAddress((void**)&x_p, g_x);

    const dim3 gemm_grid(BATCH / 64, HID / 64);  // (16, 8)

    init_kernel<<<(BATCH * HID + 255) / 256, 256>>>(input, h_p, c_p, x_p);

    int cur = 0;
    // encoder: 50 sequential LSTM steps
    for (int t = 0; t < SEQL; t++) {
        float* hin = h_p + (size_t)cur * BATCH * HID;
        float* hout = h_p + (size_t)(cur ^ 1) * BATCH * HID;
        lstm_cell_kernel<0><<<gemm_grid, 256>>>(
            input + (size_t)t * DIM, SEQL * DIM, hin,
            enc_W_ih, enc_W_hh, enc_b_ih, enc_b_hh,
            hout, c_p, enc_p + (size_t)t * HID);
        cur ^= 1;
    }
    // decoder: 30 sequential steps
    for (int s = 0; s < TLEN; s++) {
        float* hin = h_p + (size_t)cur * BATCH * HID;
        float* hout = h_p + (size_t)(cur ^ 1) * BATCH * HID;
        attn_kernel<<<BATCH, 256>>>(x_p, hin, attn_W, attn_b, enc_p, attn_p);
        comb_kernel<<<gemm_grid, 256>>>(x_p, attn_p, comb_W, comb_b, comb_p);
        lstm_cell_kernel<1><<<gemm_grid, 256>>>(
            comb_p, HID, hin,
            dec_W_ih, dec_W_hh, dec_b_ih, dec_b_hh,
            hout, c_p, nullptr);
        pred_kernel<<<BATCH / 8, 256>>>(hout, out_W, out_b, x_p, out, s);
        cur ^= 1;
    }
}

// round 3
// speedup vs baseline: 1.1179x; 1.1179x over previous
#include <cuda_runtime.h>
#include <cstddef>

#define BATCH 1024
#define SEQL  50
#define DIM   4
#define HID   512
#define TLEN  30

// ---------------- scratch (device globals: no allocation allowed) ----------
__device__ float g_enc[(size_t)BATCH * SEQL * HID];   // encoder outputs (B, L, H)
__device__ float g_hbuf[2 * BATCH * HID];             // ping-pong h
__device__ float g_c[BATCH * HID];                    // c (in-place safe)
__device__ float g_attn[BATCH * HID];                 // attn_applied
__device__ float g_comb[BATCH * HID];                 // comb (relu output)
__device__ float g_x[BATCH * DIM];                    // decoder input carry

__device__ __forceinline__ float sigf(float x) { return 1.0f / (1.0f + expf(-x)); }

// ---------------- init: h0 = c0 = 0, x0 = input[:, L-1, :] -----------------
__global__ void init_kernel(const float* __restrict__ input, float* __restrict__ h0,
                            float* __restrict__ c0, float* __restrict__ x0) {
    int i = blockIdx.x * blockDim.x + threadIdx.x;
    if (i < BATCH * HID) { h0[i] = 0.0f; c0[i] = 0.0f; }
    if (i < BATCH * DIM) {
        int b = i >> 2, d = i & 3;
        x0[i] = input[(size_t)b * SEQL * DIM + (size_t)(SEQL - 1) * DIM + d];
    }
}

// ---------------- fused LSTM cell (SGEMM-style, gate-interleaved N) --------
// Gate matrix: 1024 x 2048 (4 gates x 512 j). Block tile: BM=64 batch x
// 32 j x 4 gates (BN=128 n' columns, n' = j_local*4 + g). BK=8, double
// buffered. 256 threads, per-thread 4 batch x 8 n' (= 2 j full gate sets).
// BIG_IN=0: encoder (Din=4 folded into epilogue). BIG_IN=1: decoder
// (K=1024: h@W_hh then comb@W_ih).
template <int BIG_IN>
__global__ __launch_bounds__(256) void lstm_cell_kernel(
    const float* __restrict__ inp, int inp_stride,
    const float* __restrict__ h_in,
    const float* __restrict__ W_ih, const float* __restrict__ W_hh,
    const float* __restrict__ b_ih, const float* __restrict__ b_hh,
    float* __restrict__ h_out, float* __restrict__ c,
    float* __restrict__ enc_out /* may be null; pre-offset by t*H */) {
    __shared__ alignas(16) float As[2][8][68];    // [buf][k][b_local], pad 4
    __shared__ alignas(16) float Bs[2][8][132];   // [buf][k][n'], pad 4

    const int tid = threadIdx.x;
    const int tx = tid & 15;          // n' group: cols tx*4 and 64+tx*4
    const int ty = tid >> 4;          // batch group: rows ty*4..ty*4+3
    const int bblock = blockIdx.x * 64;
    const int jblock = blockIdx.y * 32;

    float acc[4][8];
#pragma unroll
    for (int ib = 0; ib < 4; ib++)
#pragma unroll
        for (int q = 0; q < 8; q++) acc[ib][q] = 0.0f;

    // load-thread roles: all 256 load one Bs float4; tid<128 also load As float4
    const int bn = tid >> 1;                       // n' (Bs) / b_local (As, tid<128)
    const int bk4 = (tid & 1) * 4;
    const size_t woff = (size_t)((bn & 3) * HID + jblock + (bn >> 2)) * HID + bk4;
    const size_t aoff = (size_t)(bblock + bn) * HID + bk4;

    const int NT = BIG_IN ? 128 : 64;

    float4 va = make_float4(0.f, 0.f, 0.f, 0.f), vb;
    // tile 0 (koff=0 -> always h_in / W_hh)
    vb = *(const float4*)&W_hh[woff];
    if (tid < 128) va = *(const float4*)&h_in[aoff];
    Bs[0][bk4 + 0][bn] = vb.x; Bs[0][bk4 + 1][bn] = vb.y;
    Bs[0][bk4 + 2][bn] = vb.z; Bs[0][bk4 + 3][bn] = vb.w;
    if (tid < 128) {
        As[0][bk4 + 0][bn] = va.x; As[0][bk4 + 1][bn] = va.y;
        As[0][bk4 + 2][bn] = va.z; As[0][bk4 + 3][bn] = va.w;
    }
    __syncthreads();

    for (int t = 0; t < NT; t++) {
        const int cur = t & 1;
        if (t + 1 < NT) {
            const int koff = (t + 1) * 8;
            const float* W; const float* A; int k;
            if (BIG_IN && koff >= HID) { W = W_ih; A = inp; k = koff - HID; }
            else                       { W = W_hh; A = h_in; k = koff; }
            vb = *(const float4*)&W[woff + k];
            if (tid < 128) va = *(const float4*)&A[aoff + k];
        }
#pragma unroll
        for (int kk = 0; kk < 8; kk++) {
            float a[4], blo[4], bhi[4];
            *(float4*)a   = *(const float4*)&As[cur][kk][ty * 4];
            *(float4*)blo = *(const float4*)&Bs[cur][kk][tx * 4];
            *(float4*)bhi = *(const float4*)&Bs[cur][kk][64 + tx * 4];
#pragma unroll
            for (int ib = 0; ib < 4; ib++) {
#pragma unroll
                for (int q = 0; q < 4; q++) {
                    acc[ib][q]     = fmaf(a[ib], blo[q], acc[ib][q]);
                    acc[ib][4 + q] = fmaf(a[ib], bhi[q], acc[ib][4 + q]);
                }
            }
        }
        if (t + 1 < NT) {
            const int nb = cur ^ 1;
            Bs[nb][bk4 + 0][bn] = vb.x; Bs[nb][bk4 + 1][bn] = vb.y;
            Bs[nb][bk4 + 2][bn] = vb.z; Bs[nb][bk4 + 3][bn] = vb.w;
            if (tid < 128) {
                As[nb][bk4 + 0][bn] = va.x; As[nb][bk4 + 1][bn] = va.y;
                As[nb][bk4 + 2][bn] = va.z; As[nb][bk4 + 3][bn] = va.w;
            }
        }
        __syncthreads();
    }

    if (!BIG_IN) {
        // Din=4 input projection folded in (W_ih is 2048x4, L1/L2-resident)
        float xv[4][4];
#pragma unroll
        for (int ib = 0; ib < 4; ib++) {
            const int bg = bblock + ty * 4 + ib;
#pragma unroll
            for (int k = 0; k < 4; k++) xv[ib][k] = inp[(size_t)bg * inp_stride + k];
        }
#pragma unroll
        for (int jj = 0; jj < 2; jj++) {
            const int jl = tx + 16 * jj;
#pragma unroll
            for (int g = 0; g < 4; g++) {
                const float4 w = *(const float4*)&W_ih[(size_t)(g * HID + jblock + jl) * 4];
#pragma unroll
                for (int ib = 0; ib < 4; ib++)
                    acc[ib][jj * 4 + g] += xv[ib][0] * w.x + xv[ib][1] * w.y +
                                           xv[ib][2] * w.z + xv[ib][3] * w.w;
            }
        }
    }

    // fused LSTM epilogue: per thread 4 batch rows x 2 j's, full gate sets
#pragma unroll
    for (int jj = 0; jj < 2; jj++) {
        const int jg = jblock + tx + 16 * jj;
        const float bi = b_ih[jg]           + b_hh[jg];
        const float bf = b_ih[HID + jg]     + b_hh[HID + jg];
        const float bg_ = b_ih[2 * HID + jg] + b_hh[2 * HID + jg];
        const float bo = b_ih[3 * HID + jg] + b_hh[3 * HID + jg];
#pragma unroll
        for (int ib = 0; ib < 4; ib++) {
            const int bgl = bblock + ty * 4 + ib;
            const float gi = acc[ib][jj * 4 + 0] + bi;
            const float gf = acc[ib][jj * 4 + 1] + bf;
            const float gg = acc[ib][jj * 4 + 2] + bg_;
            const float go = acc[ib][jj * 4 + 3] + bo;
            const size_t o = (size_t)bgl * HID + jg;
            const float cn = sigf(gf) * c[o] + sigf(gi) * tanhf(gg);
            const float hn = sigf(go) * tanhf(cn);
            c[o] = cn;
            h_out[o] = hn;
            if (enc_out) enc_out[(size_t)bgl * (SEQL * HID) + jg] = hn;
        }
    }
}

// ---------------- attention ------------------------------------------------
// One block per batch row. Replicates the reference's h_r scramble exactly:
// h_r[b][j] = h[2j + (b>>9)][b & 511]  (B = 2H)
__global__ void attn_kernel(const float* __restrict__ x, const float* __restrict__ h,
                            const float* __restrict__ attn_W, const float* __restrict__ attn_b,
                            const float* __restrict__ enc, float* __restrict__ attn_out) {
    __shared__ float hr[HID];
    __shared__ float w[SEQL];
    __shared__ float red[2];

    const int b = blockIdx.x;
    const int tid = threadIdx.x;
    const int bo = b >> 9;
    const int bc = b & (HID - 1);

    for (int j = tid; j < HID; j += 256)
        hr[j] = h[(size_t)(2 * j + bo) * HID + bc];
    __syncthreads();

    const int wid = tid >> 5, lane = tid & 31;
    for (int l = wid; l < SEQL; l += 8) {
        const float* wr = attn_W + (size_t)l * (HID + DIM);
        float s = 0.0f;
        for (int j = lane; j < HID; j += 32) s += hr[j] * wr[DIM + j];
#pragma unroll
        for (int off = 16; off; off >>= 1) s += __shfl_xor_sync(0xffffffffu, s, off);
        if (lane == 0) {
            s += attn_b[l] + x[b * DIM + 0] * wr[0] + x[b * DIM + 1] * wr[1] +
                 x[b * DIM + 2] * wr[2] + x[b * DIM + 3] * wr[3];
            w[l] = s;
        }
    }
    __syncthreads();
    if (tid == 0) {
        float m = w[0];
        for (int l = 1; l < SEQL; l++) m = fmaxf(m, w[l]);
        red[0] = m;
    }
    __syncthreads();
    if (tid < SEQL) w[tid] = expf(w[tid] - red[0]);
    __syncthreads();
    if (tid == 0) {
        float s = 0.0f;
        for (int l = 0; l < SEQL; l++) s += w[l];
        red[1] = 1.0f / s;
    }
    __syncthreads();
    if (tid < SEQL) w[tid] *= red[1];
    __syncthreads();

    for (int hc = tid; hc < HID; hc += 256) {
        const float* e = enc + (size_t)b * SEQL * HID + hc;
        float acc = 0.0f;
#pragma unroll
        for (int l = 0; l < SEQL; l++) acc += w[l] * e[(size_t)l * HID];
        attn_out[(size_t)b * HID + hc] = acc;
    }
}

// ---------------- comb GEMM + relu (SGEMM-style, BM=64 BN=64 BK=8) ---------
__global__ __launch_bounds__(256) void comb_kernel(
    const float* __restrict__ x, const float* __restrict__ attn,
    const float* __restrict__ comb_W, const float* __restrict__ comb_b,
    float* __restrict__ out) {
    __shared__ alignas(16) float As[2][8][68];
    __shared__ alignas(16) float Bs[2][8][68];
    const int tid = threadIdx.x;
    const int tx = tid & 15, ty = tid >> 4;
    const int bblock = blockIdx.x * 64;
    const int jblock = blockIdx.y * 64;

    float acc[4][4];
#pragma unroll
    for (int ib = 0; ib < 4; ib++)
#pragma unroll
        for (int ij = 0; ij < 4; ij++) acc[ib][ij] = 0.0f;

    // tid<128: As loader; tid>=128: Bs loader
    const int u = tid & 127;
    const int rn = u >> 1;
    const int rk4 = (u & 1) * 4;
    const size_t aoff = (size_t)(bblock + rn) * HID + rk4;
    const size_t boff = (size_t)(jblock + rn) * (HID + DIM) + DIM + rk4;
    const bool isA = tid < 128;

    float4 v;
    v = isA ? *(const float4*)&attn[aoff] : *(const float4*)&comb_W[boff];
    if (isA) {
        As[0][rk4 + 0][rn] = v.x; As[0][rk4 + 1][rn] = v.y;
        As[0][rk4 + 2][rn] = v.z; As[0][rk4 + 3][rn] = v.w;
    } else {
        Bs[0][rk4 + 0][rn] = v.x; Bs[0][rk4 + 1][rn] = v.y;
        Bs[0][rk4 + 2][rn] = v.z; Bs[0][rk4 + 3][rn] = v.w;
    }
    __syncthreads();

    const int NT = 64;
    for (int t = 0; t < NT; t++) {
        const int cur = t & 1;
        if (t + 1 < NT) {
            const int k = (t + 1) * 8;
            v = isA ? *(const float4*)&attn[aoff + k] : *(const float4*)&comb_W[boff + k];
        }
#pragma unroll
        for (int kk = 0; kk < 8; kk++) {
            float a[4], bw[4];
            *(float4*)a  = *(const float4*)&As[cur][kk][ty * 4];
            *(float4*)bw = *(const float4*)&Bs[cur][kk][tx * 4];
#pragma unroll
            for (int ib = 0; ib < 4; ib++)
#pragma unroll
                for (int ij = 0; ij < 4; ij++)
                    acc[ib][ij] = fmaf(a[ib], bw[ij], acc[ib][ij]);
        }
        if (t + 1 < NT) {
            const int nb = cur ^ 1;
            if (isA) {
                As[nb][rk4 + 0][rn] = v.x; As[nb][rk4 + 1][rn] = v.y;
                As[nb][rk4 + 2][rn] = v.z; As[nb][rk4 + 3][rn] = v.w;
            } else {
                Bs[nb][rk4 + 0][rn] = v.x; Bs[nb][rk4 + 1][rn] = v.y;
                Bs[nb][rk4 + 2][rn] = v.z; Bs[nb][rk4 + 3][rn] = v.w;
            }
        }
        __syncthreads();
    }

#pragma unroll
    for (int ib = 0; ib < 4; ib++) {
        const int bg = bblock + ty * 4 + ib;
        const float x0 = x[bg * DIM + 0], x1 = x[bg * DIM + 1];
        const float x2 = x[bg * DIM + 2], x3 = x[bg * DIM + 3];
#pragma unroll
        for (int ij = 0; ij < 4; ij++) {
            const int jg = jblock + tx * 4 + ij;
            const float4 wr = *(const float4*)&comb_W[(size_t)jg * (HID + DIM)];
            float vv = acc[ib][ij] + comb_b[jg] +
                       x0 * wr.x + x1 * wr.y + x2 * wr.z + x3 * wr.w;
            out[(size_t)bg * HID + jg] = fmaxf(vv, 0.0f);
        }
    }
}

// ---------------- pred: h @ out_W^T + out_b; writes output + next x --------
__global__ void pred_kernel(const float* __restrict__ h, const float* __restrict__ out_W,
                            const float* __restrict__ out_b, float* __restrict__ x_next,
                            float* __restrict__ out, int t) {
    const int wid = threadIdx.x >> 5, lane = threadIdx.x & 31;
    const int b = blockIdx.x * 8 + wid;
    float a0 = 0.f, a1 = 0.f, a2 = 0.f, a3 = 0.f;
    for (int j = lane; j < HID; j += 32) {
        float hv = h[(size_t)b * HID + j];
        a0 += hv * out_W[0 * HID + j];
        a1 += hv * out_W[1 * HID + j];
        a2 += hv * out_W[2 * HID + j];
        a3 += hv * out_W[3 * HID + j];
    }
#pragma unroll
    for (int off = 16; off; off >>= 1) {
        a0 += __shfl_xor_sync(0xffffffffu, a0, off);
        a1 += __shfl_xor_sync(0xffffffffu, a1, off);
        a2 += __shfl_xor_sync(0xffffffffu, a2, off);
        a3 += __shfl_xor_sync(0xffffffffu, a3, off);
    }
    if (lane == 0) {
        float v0 = a0 + out_b[0], v1 = a1 + out_b[1], v2 = a2 + out_b[2], v3 = a3 + out_b[3];
        size_t o = ((size_t)b * TLEN + t) * DIM;
        out[o + 0] = v0; out[o + 1] = v1; out[o + 2] = v2; out[o + 3] = v3;
        x_next[b * DIM + 0] = v0; x_next[b * DIM + 1] = v1;
        x_next[b * DIM + 2] = v2; x_next[b * DIM + 3] = v3;
    }
}

// ---------------- host -----------------------------------------------------
extern "C" void kernel_launch(void* const* d_in, const int* in_sizes, int n_in,
                              void* d_out, int out_size) {
    int base = 1;
    if (n_in >= 16 && in_sizes[1] == 1) base = 2;  // skip target_len scalar

    const float* input    = (const float*)d_in[0];
    const float* enc_W_ih = (const float*)d_in[base + 0];
    const float* enc_W_hh = (const float*)d_in[base + 1];
    const float* enc_b_ih = (const float*)d_in[base + 2];
    const float* enc_b_hh = (const float*)d_in[base + 3];
    const float* attn_W   = (const float*)d_in[base + 4];
    const float* attn_b   = (const float*)d_in[base + 5];
    const float* comb_W   = (const float*)d_in[base + 6];
    const float* comb_b   = (const float*)d_in[base + 7];
    const float* dec_W_ih = (const float*)d_in[base + 8];
    const float* dec_W_hh = (const float*)d_in[base + 9];
    const float* dec_b_ih = (const float*)d_in[base + 10];
    const float* dec_b_hh = (const float*)d_in[base + 11];
    const float* out_W    = (const float*)d_in[base + 12];
    const float* out_b    = (const float*)d_in[base + 13];
    float* out = (float*)d_out;

    float *enc_p, *h_p, *c_p, *attn_p, *comb_p, *x_p;
    cudaGetSymbolAddress((void**)&enc_p, g_enc);
    cudaGetSymbolAddress((void**)&h_p, g_hbuf);
    cudaGetSymbolAddress((void**)&c_p, g_c);
    cudaGetSymbolAddress((void**)&attn_p, g_attn);
    cudaGetSymbolAddress((void**)&comb_p, g_comb);
    cudaGetSymbolAddress((void**)&x_p, g_x);

    const dim3 lstm_grid(BATCH / 64, HID / 32);   // (16, 16)
    const dim3 comb_grid(BATCH / 64, HID / 64);   // (16, 8)

    init_kernel<<<(BATCH * HID + 255) / 256, 256>>>(input, h_p, c_p, x_p);

    int cur = 0;
    // encoder: 50 sequential LSTM steps
    for (int t = 0; t < SEQL; t++) {
        float* hin = h_p + (size_t)cur * BATCH * HID;
        float* hout = h_p + (size_t)(cur ^ 1) * BATCH * HID;
        lstm_cell_kernel<0><<<lstm_grid, 256>>>(
            input + (size_t)t * DIM, SEQL * DIM, hin,
            enc_W_ih, enc_W_hh, enc_b_ih, enc_b_hh,
            hout, c_p, enc_p + (size_t)t * HID);
        cur ^= 1;
    }
    // decoder: 30 sequential steps
    for (int s = 0; s < TLEN; s++) {
        float* hin = h_p + (size_t)cur * BATCH * HID;
        float* hout = h_p + (size_t)(cur ^ 1) * BATCH * HID;
        attn_kernel<<<BATCH, 256>>>(x_p, hin, attn_W, attn_b, enc_p, attn_p);
        comb_kernel<<<comb_grid, 256>>>(x_p, attn_p, comb_W, comb_b, comb_p);
        lstm_cell_kernel<1><<<lstm_grid, 256>>>(
            comb_p, HID, hin,
            dec_W_ih, dec_W_hh, dec_b_ih, dec_b_hh,
            hout, c_p, nullptr);
        pred_kernel<<<BATCH / 8, 256>>>(hout, out_W, out_b, x_p, out, s);
        cur ^= 1;
    }
}

// round 4
// speedup vs baseline: 1.1987x; 1.0723x over previous
#include <cuda_runtime.h>
#include <cstddef>

#define BATCH 1024
#define SEQL  50
#define DIM   4
#define HID   512
#define TLEN  30

// ---------------- scratch (device globals: no allocation allowed) ----------
__device__ float g_enc[(size_t)BATCH * SEQL * HID];   // encoder outputs (B, L, H)
__device__ float g_hbuf[2 * BATCH * HID];             // ping-pong h
__device__ float g_c[BATCH * HID];                    // c (in-place safe)
__device__ float g_attn[BATCH * HID];                 // attn_applied
__device__ float g_comb[BATCH * HID];                 // comb (relu output)
__device__ float g_x[BATCH * DIM];                    // decoder input carry
__device__ float g_gates[(size_t)BATCH * 4 * HID];    // h@W_hh partial gates

__device__ __forceinline__ float sigf(float x) { return 1.0f / (1.0f + expf(-x)); }

// ---------------- init: h0 = c0 = 0, x0 = input[:, L-1, :] -----------------
__global__ void init_kernel(const float* __restrict__ input, float* __restrict__ h0,
                            float* __restrict__ c0, float* __restrict__ x0) {
    int i = blockIdx.x * blockDim.x + threadIdx.x;
    if (i < BATCH * HID) { h0[i] = 0.0f; c0[i] = 0.0f; }
    if (i < BATCH * DIM) {
        int b = i >> 2, d = i & 3;
        x0[i] = input[(size_t)b * SEQL * DIM + (size_t)(SEQL - 1) * DIM + d];
    }
}

// ---------------- encoder fused LSTM cell (SGEMM, gate-interleaved N) ------
// Block tile: BM=64 batch x 32 j x 4 gates (BN=128 n'), BK=8, double
// buffered, 256 threads, per-thread 4 batch x 8 n'. Din=4 folded in epilogue.
__global__ __launch_bounds__(256) void enc_lstm_kernel(
    const float* __restrict__ inp, int inp_stride,
    const float* __restrict__ h_in,
    const float* __restrict__ W_ih, const float* __restrict__ W_hh,
    const float* __restrict__ b_ih, const float* __restrict__ b_hh,
    float* __restrict__ h_out, float* __restrict__ c,
    float* __restrict__ enc_out /* pre-offset by t*H */) {
    __shared__ alignas(16) float As[2][8][68];
    __shared__ alignas(16) float Bs[2][8][132];

    const int tid = threadIdx.x;
    const int tx = tid & 15;
    const int ty = tid >> 4;
    const int bblock = blockIdx.x * 64;
    const int jblock = blockIdx.y * 32;

    float acc[4][8];
#pragma unroll
    for (int ib = 0; ib < 4; ib++)
#pragma unroll
        for (int q = 0; q < 8; q++) acc[ib][q] = 0.0f;

    const int bn = tid >> 1;
    const int bk4 = (tid & 1) * 4;
    const size_t woff = (size_t)((bn & 3) * HID + jblock + (bn >> 2)) * HID + bk4;
    const size_t aoff = (size_t)(bblock + bn) * HID + bk4;

    float4 va = make_float4(0.f, 0.f, 0.f, 0.f), vb;
    vb = *(const float4*)&W_hh[woff];
    if (tid < 128) va = *(const float4*)&h_in[aoff];
    Bs[0][bk4 + 0][bn] = vb.x; Bs[0][bk4 + 1][bn] = vb.y;
    Bs[0][bk4 + 2][bn] = vb.z; Bs[0][bk4 + 3][bn] = vb.w;
    if (tid < 128) {
        As[0][bk4 + 0][bn] = va.x; As[0][bk4 + 1][bn] = va.y;
        As[0][bk4 + 2][bn] = va.z; As[0][bk4 + 3][bn] = va.w;
    }
    __syncthreads();

    const int NT = 64;
    for (int t = 0; t < NT; t++) {
        const int cur = t & 1;
        if (t + 1 < NT) {
            const int k = (t + 1) * 8;
            vb = *(const float4*)&W_hh[woff + k];
            if (tid < 128) va = *(const float4*)&h_in[aoff + k];
        }
#pragma unroll
        for (int kk = 0; kk < 8; kk++) {
            float a[4], blo[4], bhi[4];
            *(float4*)a   = *(const float4*)&As[cur][kk][ty * 4];
            *(float4*)blo = *(const float4*)&Bs[cur][kk][tx * 4];
            *(float4*)bhi = *(const float4*)&Bs[cur][kk][64 + tx * 4];
#pragma unroll
            for (int ib = 0; ib < 4; ib++) {
#pragma unroll
                for (int q = 0; q < 4; q++) {
                    acc[ib][q]     = fmaf(a[ib], blo[q], acc[ib][q]);
                    acc[ib][4 + q] = fmaf(a[ib], bhi[q], acc[ib][4 + q]);
                }
            }
        }
        if (t + 1 < NT) {
            const int nb = cur ^ 1;
            Bs[nb][bk4 + 0][bn] = vb.x; Bs[nb][bk4 + 1][bn] = vb.y;
            Bs[nb][bk4 + 2][bn] = vb.z; Bs[nb][bk4 + 3][bn] = vb.w;
            if (tid < 128) {
                As[nb][bk4 + 0][bn] = va.x; As[nb][bk4 + 1][bn] = va.y;
                As[nb][bk4 + 2][bn] = va.z; As[nb][bk4 + 3][bn] = va.w;
            }
        }
        __syncthreads();
    }

    // Din=4 input projection folded in
    float xv[4][4];
#pragma unroll
    for (int ib = 0; ib < 4; ib++) {
        const int bg = bblock + ty * 4 + ib;
#pragma unroll
        for (int k = 0; k < 4; k++) xv[ib][k] = inp[(size_t)bg * inp_stride + k];
    }
#pragma unroll
    for (int jj = 0; jj < 2; jj++) {
        const int jl = tx + 16 * jj;
#pragma unroll
        for (int g = 0; g < 4; g++) {
            const float4 w = *(const float4*)&W_ih[(size_t)(g * HID + jblock + jl) * 4];
#pragma unroll
            for (int ib = 0; ib < 4; ib++)
                acc[ib][jj * 4 + g] += xv[ib][0] * w.x + xv[ib][1] * w.y +
                                       xv[ib][2] * w.z + xv[ib][3] * w.w;
        }
    }

#pragma unroll
    for (int jj = 0; jj < 2; jj++) {
        const int jg = jblock + tx + 16 * jj;
        const float bi  = b_ih[jg]            + b_hh[jg];
        const float bf  = b_ih[HID + jg]      + b_hh[HID + jg];
        const float bg_ = b_ih[2 * HID + jg]  + b_hh[2 * HID + jg];
        const float bo  = b_ih[3 * HID + jg]  + b_hh[3 * HID + jg];
#pragma unroll
        for (int ib = 0; ib < 4; ib++) {
            const int bgl = bblock + ty * 4 + ib;
            const float gi = acc[ib][jj * 4 + 0] + bi;
            const float gf = acc[ib][jj * 4 + 1] + bf;
            const float gg = acc[ib][jj * 4 + 2] + bg_;
            const float go = acc[ib][jj * 4 + 3] + bo;
            const size_t o = (size_t)bgl * HID + jg;
            const float cn = sigf(gf) * c[o] + sigf(gi) * tanhf(gg);
            const float hn = sigf(go) * tanhf(cn);
            c[o] = cn;
            h_out[o] = hn;
            enc_out[(size_t)bgl * (SEQL * HID) + jg] = hn;
        }
    }
}

// ---------------- decoder fused: h@W_hh gates || attention -----------------
// Blocks [0,256): GEMM h_in @ W_hh^T -> raw gates scratch (no epilogue).
// Blocks [256,1280): attention for batch row b = blockIdx.x - 256.
// Both depend only on h_in/x -> full concurrency on chip.
__global__ __launch_bounds__(256) void dec_fused_kernel(
    const float* __restrict__ x, const float* __restrict__ h_in,
    const float* __restrict__ W_hh,
    const float* __restrict__ attn_W, const float* __restrict__ attn_b,
    const float* __restrict__ enc,
    float* __restrict__ gates, float* __restrict__ attn_out) {
    __shared__ alignas(16) float As[2][8][68];
    __shared__ alignas(16) float Bs[2][8][132];
    __shared__ float hr[HID];
    __shared__ float w[SEQL];
    __shared__ float red[2];

    const int tid = threadIdx.x;

    if (blockIdx.x < 256) {
        // ----- h @ W_hh^T gate partial GEMM -----
        const int tx = tid & 15;
        const int ty = tid >> 4;
        const int bblock = (blockIdx.x & 15) * 64;
        const int jblock = (blockIdx.x >> 4) * 32;

        float acc[4][8];
#pragma unroll
        for (int ib = 0; ib < 4; ib++)
#pragma unroll
            for (int q = 0; q < 8; q++) acc[ib][q] = 0.0f;

        const int bn = tid >> 1;
        const int bk4 = (tid & 1) * 4;
        const size_t woff = (size_t)((bn & 3) * HID + jblock + (bn >> 2)) * HID + bk4;
        const size_t aoff = (size_t)(bblock + bn) * HID + bk4;

        float4 va = make_float4(0.f, 0.f, 0.f, 0.f), vb;
        vb = *(const float4*)&W_hh[woff];
        if (tid < 128) va = *(const float4*)&h_in[aoff];
        Bs[0][bk4 + 0][bn] = vb.x; Bs[0][bk4 + 1][bn] = vb.y;
        Bs[0][bk4 + 2][bn] = vb.z; Bs[0][bk4 + 3][bn] = vb.w;
        if (tid < 128) {
            As[0][bk4 + 0][bn] = va.x; As[0][bk4 + 1][bn] = va.y;
            As[0][bk4 + 2][bn] = va.z; As[0][bk4 + 3][bn] = va.w;
        }
        __syncthreads();

        const int NT = 64;
        for (int t = 0; t < NT; t++) {
            const int cur = t & 1;
            if (t + 1 < NT) {
                const int k = (t + 1) * 8;
                vb = *(const float4*)&W_hh[woff + k];
                if (tid < 128) va = *(const float4*)&h_in[aoff + k];
            }
#pragma unroll
            for (int kk = 0; kk < 8; kk++) {
                float a[4], blo[4], bhi[4];
                *(float4*)a   = *(const float4*)&As[cur][kk][ty * 4];
                *(float4*)blo = *(const float4*)&Bs[cur][kk][tx * 4];
                *(float4*)bhi = *(const float4*)&Bs[cur][kk][64 + tx * 4];
#pragma unroll
                for (int ib = 0; ib < 4; ib++) {
#pragma unroll
                    for (int q = 0; q < 4; q++) {
                        acc[ib][q]     = fmaf(a[ib], blo[q], acc[ib][q]);
                        acc[ib][4 + q] = fmaf(a[ib], bhi[q], acc[ib][4 + q]);
                    }
                }
            }
            if (t + 1 < NT) {
                const int nb = cur ^ 1;
                Bs[nb][bk4 + 0][bn] = vb.x; Bs[nb][bk4 + 1][bn] = vb.y;
                Bs[nb][bk4 + 2][bn] = vb.z; Bs[nb][bk4 + 3][bn] = vb.w;
                if (tid < 128) {
                    As[nb][bk4 + 0][bn] = va.x; As[nb][bk4 + 1][bn] = va.y;
                    As[nb][bk4 + 2][bn] = va.z; As[nb][bk4 + 3][bn] = va.w;
                }
            }
            __syncthreads();
        }

#pragma unroll
        for (int jj = 0; jj < 2; jj++) {
            const int jg = jblock + tx + 16 * jj;
#pragma unroll
            for (int ib = 0; ib < 4; ib++) {
                const int bgl = bblock + ty * 4 + ib;
                float* gp = gates + (size_t)bgl * (4 * HID) + jg;
                gp[0]       = acc[ib][jj * 4 + 0];
                gp[HID]     = acc[ib][jj * 4 + 1];
                gp[2 * HID] = acc[ib][jj * 4 + 2];
                gp[3 * HID] = acc[ib][jj * 4 + 3];
            }
        }
    } else {
        // ----- attention for one batch row -----
        // h_r scramble: h_r[b][j] = h[2j + (b>>9)][b & 511]  (B = 2H)
        const int b = blockIdx.x - 256;
        const int bo = b >> 9;
        const int bc = b & (HID - 1);

        for (int j = tid; j < HID; j += 256)
            hr[j] = h_in[(size_t)(2 * j + bo) * HID + bc];
        __syncthreads();

        const int wid = tid >> 5, lane = tid & 31;
        for (int l = wid; l < SEQL; l += 8) {
            const float* wr = attn_W + (size_t)l * (HID + DIM);
            float s = 0.0f;
            for (int j = lane; j < HID; j += 32) s += hr[j] * wr[DIM + j];
#pragma unroll
            for (int off = 16; off; off >>= 1) s += __shfl_xor_sync(0xffffffffu, s, off);
            if (lane == 0) {
                s += attn_b[l] + x[b * DIM + 0] * wr[0] + x[b * DIM + 1] * wr[1] +
                     x[b * DIM + 2] * wr[2] + x[b * DIM + 3] * wr[3];
                w[l] = s;
            }
        }
        __syncthreads();
        if (tid == 0) {
            float m = w[0];
            for (int l = 1; l < SEQL; l++) m = fmaxf(m, w[l]);
            red[0] = m;
        }
        __syncthreads();
        if (tid < SEQL) w[tid] = expf(w[tid] - red[0]);
        __syncthreads();
        if (tid == 0) {
            float s = 0.0f;
            for (int l = 0; l < SEQL; l++) s += w[l];
            red[1] = 1.0f / s;
        }
        __syncthreads();
        if (tid < SEQL) w[tid] *= red[1];
        __syncthreads();

        for (int hc = tid; hc < HID; hc += 256) {
            const float* e = enc + (size_t)b * SEQL * HID + hc;
            float acc = 0.0f;
#pragma unroll
            for (int l = 0; l < SEQL; l++) acc += w[l] * e[(size_t)l * HID];
            attn_out[(size_t)b * HID + hc] = acc;
        }
    }
}

// ---------------- comb GEMM + relu (BM=64 BN=64 BK=8) ----------------------
__global__ __launch_bounds__(256) void comb_kernel(
    const float* __restrict__ x, const float* __restrict__ attn,
    const float* __restrict__ comb_W, const float* __restrict__ comb_b,
    float* __restrict__ out) {
    __shared__ alignas(16) float As[2][8][68];
    __shared__ alignas(16) float Bs[2][8][68];
    const int tid = threadIdx.x;
    const int tx = tid & 15, ty = tid >> 4;
    const int bblock = blockIdx.x * 64;
    const int jblock = blockIdx.y * 64;

    float acc[4][4];
#pragma unroll
    for (int ib = 0; ib < 4; ib++)
#pragma unroll
        for (int ij = 0; ij < 4; ij++) acc[ib][ij] = 0.0f;

    const int u = tid & 127;
    const int rn = u >> 1;
    const int rk4 = (u & 1) * 4;
    const size_t aoff = (size_t)(bblock + rn) * HID + rk4;
    const size_t boff = (size_t)(jblock + rn) * (HID + DIM) + DIM + rk4;
    const bool isA = tid < 128;

    float4 v;
    v = isA ? *(const float4*)&attn[aoff] : *(const float4*)&comb_W[boff];
    if (isA) {
        As[0][rk4 + 0][rn] = v.x; As[0][rk4 + 1][rn] = v.y;
        As[0][rk4 + 2][rn] = v.z; As[0][rk4 + 3][rn] = v.w;
    } else {
        Bs[0][rk4 + 0][rn] = v.x; Bs[0][rk4 + 1][rn] = v.y;
        Bs[0][rk4 + 2][rn] = v.z; Bs[0][rk4 + 3][rn] = v.w;
    }
    __syncthreads();

    const int NT = 64;
    for (int t = 0; t < NT; t++) {
        const int cur = t & 1;
        if (t + 1 < NT) {
            const int k = (t + 1) * 8;
            v = isA ? *(const float4*)&attn[aoff + k] : *(const float4*)&comb_W[boff + k];
        }
#pragma unroll
        for (int kk = 0; kk < 8; kk++) {
            float a[4], bw[4];
            *(float4*)a  = *(const float4*)&As[cur][kk][ty * 4];
            *(float4*)bw = *(const float4*)&Bs[cur][kk][tx * 4];
#pragma unroll
            for (int ib = 0; ib < 4; ib++)
#pragma unroll
                for (int ij = 0; ij < 4; ij++)
                    acc[ib][ij] = fmaf(a[ib], bw[ij], acc[ib][ij]);
        }
        if (t + 1 < NT) {
            const int nb = cur ^ 1;
            if (isA) {
                As[nb][rk4 + 0][rn] = v.x; As[nb][rk4 + 1][rn] = v.y;
                As[nb][rk4 + 2][rn] = v.z; As[nb][rk4 + 3][rn] = v.w;
            } else {
                Bs[nb][rk4 + 0][rn] = v.x; Bs[nb][rk4 + 1][rn] = v.y;
                Bs[nb][rk4 + 2][rn] = v.z; Bs[nb][rk4 + 3][rn] = v.w;
            }
        }
        __syncthreads();
    }

#pragma unroll
    for (int ib = 0; ib < 4; ib++) {
        const int bg = bblock + ty * 4 + ib;
        const float x0 = x[bg * DIM + 0], x1 = x[bg * DIM + 1];
        const float x2 = x[bg * DIM + 2], x3 = x[bg * DIM + 3];
#pragma unroll
        for (int ij = 0; ij < 4; ij++) {
            const int jg = jblock + tx * 4 + ij;
            const float4 wr = *(const float4*)&comb_W[(size_t)jg * (HID + DIM)];
            float vv = acc[ib][ij] + comb_b[jg] +
                       x0 * wr.x + x1 * wr.y + x2 * wr.z + x3 * wr.w;
            out[(size_t)bg * HID + jg] = fmaxf(vv, 0.0f);
        }
    }
}

// ---------------- decoder finish: comb@W_ih + gates + LSTM epilogue --------
__global__ __launch_bounds__(256) void lstm_finish_kernel(
    const float* __restrict__ comb, const float* __restrict__ h_unused,
    const float* __restrict__ W_ih,
    const float* __restrict__ b_ih, const float* __restrict__ b_hh,
    const float* __restrict__ gates,
    float* __restrict__ h_out, float* __restrict__ c) {
    __shared__ alignas(16) float As[2][8][68];
    __shared__ alignas(16) float Bs[2][8][132];

    const int tid = threadIdx.x;
    const int tx = tid & 15;
    const int ty = tid >> 4;
    const int bblock = blockIdx.x * 64;
    const int jblock = blockIdx.y * 32;

    float acc[4][8];
#pragma unroll
    for (int ib = 0; ib < 4; ib++)
#pragma unroll
        for (int q = 0; q < 8; q++) acc[ib][q] = 0.0f;

    const int bn = tid >> 1;
    const int bk4 = (tid & 1) * 4;
    const size_t woff = (size_t)((bn & 3) * HID + jblock + (bn >> 2)) * HID + bk4;
    const size_t aoff = (size_t)(bblock + bn) * HID + bk4;

    float4 va = make_float4(0.f, 0.f, 0.f, 0.f), vb;
    vb = *(const float4*)&W_ih[woff];
    if (tid < 128) va = *(const float4*)&comb[aoff];
    Bs[0][bk4 + 0][bn] = vb.x; Bs[0][bk4 + 1][bn] = vb.y;
    Bs[0][bk4 + 2][bn] = vb.z; Bs[0][bk4 + 3][bn] = vb.w;
    if (tid < 128) {
        As[0][bk4 + 0][bn] = va.x; As[0][bk4 + 1][bn] = va.y;
        As[0][bk4 + 2][bn] = va.z; As[0][bk4 + 3][bn] = va.w;
    }
    __syncthreads();

    const int NT = 64;
    for (int t = 0; t < NT; t++) {
        const int cur = t & 1;
        if (t + 1 < NT) {
            const int k = (t + 1) * 8;
            vb = *(const float4*)&W_ih[woff + k];
            if (tid < 128) va = *(const float4*)&comb[aoff + k];
        }
#pragma unroll
        for (int kk = 0; kk < 8; kk++) {
            float a[4], blo[4], bhi[4];
            *(float4*)a   = *(const float4*)&As[cur][kk][ty * 4];
            *(float4*)blo = *(const float4*)&Bs[cur][kk][tx * 4];
            *(float4*)bhi = *(const float4*)&Bs[cur][kk][64 + tx * 4];
#pragma unroll
            for (int ib = 0; ib < 4; ib++) {
#pragma unroll
                for (int q = 0; q < 4; q++) {
                    acc[ib][q]     = fmaf(a[ib], blo[q], acc[ib][q]);
                    acc[ib][4 + q] = fmaf(a[ib], bhi[q], acc[ib][4 + q]);
                }
            }
        }
        if (t + 1 < NT) {
            const int nb = cur ^ 1;
            Bs[nb][bk4 + 0][bn] = vb.x; Bs[nb][bk4 + 1][bn] = vb.y;
            Bs[nb][bk4 + 2][bn] = vb.z; Bs[nb][bk4 + 3][bn] = vb.w;
            if (tid < 128) {
                As[nb][bk4 + 0][bn] = va.x; As[nb][bk4 + 1][bn] = va.y;
                As[nb][bk4 + 2][bn] = va.z; As[nb][bk4 + 3][bn] = va.w;
            }
        }
        __syncthreads();
    }

#pragma unroll
    for (int jj = 0; jj < 2; jj++) {
        const int jg = jblock + tx + 16 * jj;
        const float bi  = b_ih[jg]            + b_hh[jg];
        const float bf  = b_ih[HID + jg]      + b_hh[HID + jg];
        const float bg_ = b_ih[2 * HID + jg]  + b_hh[2 * HID + jg];
        const float bo  = b_ih[3 * HID + jg]  + b_hh[3 * HID + jg];
#pragma unroll
        for (int ib = 0; ib < 4; ib++) {
            const int bgl = bblock + ty * 4 + ib;
            const float* gp = gates + (size_t)bgl * (4 * HID) + jg;
            const float gi = acc[ib][jj * 4 + 0] + gp[0]       + bi;
            const float gf = acc[ib][jj * 4 + 1] + gp[HID]     + bf;
            const float gg = acc[ib][jj * 4 + 2] + gp[2 * HID] + bg_;
            const float go = acc[ib][jj * 4 + 3] + gp[3 * HID] + bo;
            const size_t o = (size_t)bgl * HID + jg;
            const float cn = sigf(gf) * c[o] + sigf(gi) * tanhf(gg);
            const float hn = sigf(go) * tanhf(cn);
            c[o] = cn;
            h_out[o] = hn;
        }
    }
}

// ---------------- pred: h @ out_W^T + out_b; writes output + next x --------
__global__ void pred_kernel(const float* __restrict__ h, const float* __restrict__ out_W,
                            const float* __restrict__ out_b, float* __restrict__ x_next,
                            float* __restrict__ out, int t) {
    const int wid = threadIdx.x >> 5, lane = threadIdx.x & 31;
    const int b = blockIdx.x * 8 + wid;
    float a0 = 0.f, a1 = 0.f, a2 = 0.f, a3 = 0.f;
    for (int j = lane; j < HID; j += 32) {
        float hv = h[(size_t)b * HID + j];
        a0 += hv * out_W[0 * HID + j];
        a1 += hv * out_W[1 * HID + j];
        a2 += hv * out_W[2 * HID + j];
        a3 += hv * out_W[3 * HID + j];
    }
#pragma unroll
    for (int off = 16; off; off >>= 1) {
        a0 += __shfl_xor_sync(0xffffffffu, a0, off);
        a1 += __shfl_xor_sync(0xffffffffu, a1, off);
        a2 += __shfl_xor_sync(0xffffffffu, a2, off);
        a3 += __shfl_xor_sync(0xffffffffu, a3, off);
    }
    if (lane == 0) {
        float v0 = a0 + out_b[0], v1 = a1 + out_b[1], v2 = a2 + out_b[2], v3 = a3 + out_b[3];
        size_t o = ((size_t)b * TLEN + t) * DIM;
        out[o + 0] = v0; out[o + 1] = v1; out[o + 2] = v2; out[o + 3] = v3;
        x_next[b * DIM + 0] = v0; x_next[b * DIM + 1] = v1;
        x_next[b * DIM + 2] = v2; x_next[b * DIM + 3] = v3;
    }
}

// ---------------- host -----------------------------------------------------
extern "C" void kernel_launch(void* const* d_in, const int* in_sizes, int n_in,
                              void* d_out, int out_size) {
    int base = 1;
    if (n_in >= 16 && in_sizes[1] == 1) base = 2;  // skip target_len scalar

    const float* input    = (const float*)d_in[0];
    const float* enc_W_ih = (const float*)d_in[base + 0];
    const float* enc_W_hh = (const float*)d_in[base + 1];
    const float* enc_b_ih = (const float*)d_in[base + 2];
    const float* enc_b_hh = (const float*)d_in[base + 3];
    const float* attn_W   = (const float*)d_in[base + 4];
    const float* attn_b   = (const float*)d_in[base + 5];
    const float* comb_W   = (const float*)d_in[base + 6];
    const float* comb_b   = (const float*)d_in[base + 7];
    const float* dec_W_ih = (const float*)d_in[base + 8];
    const float* dec_W_hh = (const float*)d_in[base + 9];
    const float* dec_b_ih = (const float*)d_in[base + 10];
    const float* dec_b_hh = (const float*)d_in[base + 11];
    const float* out_W    = (const float*)d_in[base + 12];
    const float* out_b    = (const float*)d_in[base + 13];
    float* out = (float*)d_out;

    float *enc_p, *h_p, *c_p, *attn_p, *comb_p, *x_p, *gates_p;
    cudaGetSymbolAddress((void**)&enc_p, g_enc);
    cudaGetSymbolAddress((void**)&h_p, g_hbuf);
    cudaGetSymbolAddress((void**)&c_p, g_c);
    cudaGetSymbolAddress((void**)&attn_p, g_attn);
    cudaGetSymbolAddress((void**)&comb_p, g_comb);
    cudaGetSymbolAddress((void**)&x_p, g_x);
    cudaGetSymbolAddress((void**)&gates_p, g_gates);

    const dim3 lstm_grid(BATCH / 64, HID / 32);   // (16, 16)
    const dim3 comb_grid(BATCH / 64, HID / 64);   // (16, 8)

    init_kernel<<<(BATCH * HID + 255) / 256, 256>>>(input, h_p, c_p, x_p);

    int cur = 0;
    // encoder: 50 sequential LSTM steps
    for (int t = 0; t < SEQL; t++) {
        float* hin = h_p + (size_t)cur * BATCH * HID;
        float* hout = h_p + (size_t)(cur ^ 1) * BATCH * HID;
        enc_lstm_kernel<<<lstm_grid, 256>>>(
            input + (size_t)t * DIM, SEQL * DIM, hin,
            enc_W_ih, enc_W_hh, enc_b_ih, enc_b_hh,
            hout, c_p, enc_p + (size_t)t * HID);
        cur ^= 1;
    }
    // decoder: 30 sequential steps; h-GEMM and attention run concurrently
    for (int s = 0; s < TLEN; s++) {
        float* hin = h_p + (size_t)cur * BATCH * HID;
        float* hout = h_p + (size_t)(cur ^ 1) * BATCH * HID;
        dec_fused_kernel<<<256 + BATCH, 256>>>(
            x_p, hin, dec_W_hh, attn_W, attn_b, enc_p, gates_p, attn_p);
        comb_kernel<<<comb_grid, 256>>>(x_p, attn_p, comb_W, comb_b, comb_p);
        lstm_finish_kernel<<<lstm_grid, 256>>>(
            comb_p, hin, dec_W_ih, dec_b_ih, dec_b_hh, gates_p, hout, c_p);
        pred_kernel<<<BATCH / 8, 256>>>(hout, out_W, out_b, x_p, out, s);
        cur ^= 1;
    }
}

// round 11
// speedup vs baseline: 1.6556x; 1.3811x over previous
#include <cuda_runtime.h>
#include <cuda_bf16.h>
#include <cstddef>
#include <cstdint>

#define BATCH 1024
#define SEQL  50
#define DIM   4
#define HID   512
#define TLEN  30
#define HS    (BATCH * HID)

// GEMM config: CTA 128x128, K-chunks of 64 bf16 (128B rows), 3 split terms
#define NCHUNK  24                  // 3 terms x (512/64)
#define TILE_B  16384               // 128 rows x 128 bytes
#define DSMEM_B 66560               // max(4 tiles = 64KB, stage 128x130 fp32)

// ---------------- scratch (device globals; no allocation allowed) ----------
__device__ float g_enc[(size_t)BATCH * SEQL * HID];       // encoder outputs fp32
__device__ float g_h[HS];                                  // h fp32
__device__ float g_c[HS];                                  // c fp32
__device__ float g_x[BATCH * DIM];                         // decoder input carry
__device__ float g_gates[(size_t)BATCH * 4 * HID];         // dec h@W_hh raw gates
__device__ __align__(256) __nv_bfloat16 g_hs_hi[2 * HS];   // h split ping-pong
__device__ __align__(256) __nv_bfloat16 g_hs_lo[2 * HS];
__device__ __align__(256) __nv_bfloat16 g_attn_hi[HS];
__device__ __align__(256) __nv_bfloat16 g_attn_lo[HS];
__device__ __align__(256) __nv_bfloat16 g_comb_hi[HS];
__device__ __align__(256) __nv_bfloat16 g_comb_lo[HS];
__device__ __align__(256) __nv_bfloat16 g_wehh_hi[4 * HID * HID];  // enc W_hh interleaved
__device__ __align__(256) __nv_bfloat16 g_wehh_lo[4 * HID * HID];
__device__ __align__(256) __nv_bfloat16 g_wdhh_hi[4 * HID * HID];  // dec W_hh
__device__ __align__(256) __nv_bfloat16 g_wdhh_lo[4 * HID * HID];
__device__ __align__(256) __nv_bfloat16 g_wdih_hi[4 * HID * HID];  // dec W_ih
__device__ __align__(256) __nv_bfloat16 g_wdih_lo[4 * HID * HID];
__device__ __align__(256) __nv_bfloat16 g_wcmb_hi[HID * HID];      // comb_W (attn part)
__device__ __align__(256) __nv_bfloat16 g_wcmb_lo[HID * HID];

__device__ __forceinline__ float sigf(float x) { return 1.0f / (1.0f + expf(-x)); }

__device__ __forceinline__ void bf_split(float x, __nv_bfloat16& h, __nv_bfloat16& l) {
    h = __float2bfloat16(x);
    l = __float2bfloat16(x - __bfloat162float(h));
}

__device__ __forceinline__ uint32_t smem_u32(const void* p) {
    uint32_t a;
    asm("{ .reg .u64 t; cvta.to.shared.u64 t, %1; cvt.u32.u64 %0, t; }" : "=r"(a) : "l"(p));
    return a;
}
__device__ __forceinline__ void sts128(uint32_t addr, uint4 v) {
    asm volatile("st.shared.v4.b32 [%0], {%1,%2,%3,%4};"
                 :: "r"(addr), "r"(v.x), "r"(v.y), "r"(v.z), "r"(v.w) : "memory");
}
__device__ __forceinline__ void ldm4(uint32_t& r0, uint32_t& r1, uint32_t& r2, uint32_t& r3,
                                     uint32_t addr) {
    asm volatile("ldmatrix.sync.aligned.m8n8.x4.shared.b16 {%0,%1,%2,%3}, [%4];"
                 : "=r"(r0), "=r"(r1), "=r"(r2), "=r"(r3) : "r"(addr));
}
__device__ __forceinline__ void mma16816(float* c, uint32_t a0, uint32_t a1, uint32_t a2,
                                         uint32_t a3, uint32_t b0, uint32_t b1) {
    asm volatile(
        "mma.sync.aligned.m16n8k16.row.col.f32.bf16.bf16.f32 "
        "{%0,%1,%2,%3}, {%4,%5,%6,%7}, {%8,%9}, {%0,%1,%2,%3};"
        : "+f"(c[0]), "+f"(c[1]), "+f"(c[2]), "+f"(c[3])
        : "r"(a0), "r"(a1), "r"(a2), "r"(a3), "r"(b0), "r"(b1));
}

// ---------------- prep: split weights to bf16 hi/lo ------------------------
// gate weights: src [g*512+j][k] fp32 -> dst interleaved [j*4+g][k]
__global__ void split_gate_w(const float* __restrict__ W,
                             __nv_bfloat16* __restrict__ hi, __nv_bfloat16* __restrict__ lo) {
    int idx = blockIdx.x * 256 + threadIdx.x;
    if (idx >= 4 * HID * HID) return;
    int k = idx & 511;
    int row = idx >> 9;            // g*512 + j
    int g = row >> 9, j = row & 511;
    __nv_bfloat16 h, l;
    bf_split(W[idx], h, l);
    size_t d = ((size_t)(j * 4 + g)) * HID + k;
    hi[d] = h; lo[d] = l;
}
// comb_W: src [j][516] (cols 4..515 = attn part) -> dst [j][k]
__global__ void split_comb_w(const float* __restrict__ W,
                             __nv_bfloat16* __restrict__ hi, __nv_bfloat16* __restrict__ lo) {
    int idx = blockIdx.x * 256 + threadIdx.x;
    if (idx >= HID * HID) return;
    int j = idx >> 9, k = idx & 511;
    __nv_bfloat16 h, l;
    bf_split(W[(size_t)j * (HID + DIM) + DIM + k], h, l);
    hi[idx] = h; lo[idx] = l;
}

// ---------------- init ------------------------------------------------------
__global__ void init_kernel(const float* __restrict__ input, float* __restrict__ c0,
                            __nv_bfloat16* __restrict__ hh, __nv_bfloat16* __restrict__ hl,
                            float* __restrict__ x0) {
    int i = blockIdx.x * blockDim.x + threadIdx.x;
    if (i < HS) {
        c0[i] = 0.0f;
        hh[i] = __float2bfloat16(0.0f);
        hl[i] = __float2bfloat16(0.0f);
    }
    if (i < BATCH * DIM) {
        int b = i >> 2, d = i & 3;
        x0[i] = input[(size_t)b * SEQL * DIM + (size_t)(SEQL - 1) * DIM + d];
    }
}

// ---------------- mma.sync GEMM + fused epilogues ---------------------------
// C[128 x 128] per CTA via m16n8k16 bf16 HMMA, 3-term split over K (24 chunks).
// A rows: batch (k-major split bf16); B rows: n' (gate-interleaved or j).
// EPI 0: encoder LSTM (Din=4 fold + biases; writes c,h,h_hi,h_lo,enc_out)
// EPI 1: raw gates out (dec h@W_hh) via out_c
// EPI 2: comb (x-fold + bias + relu; writes split)
// EPI 3: dec LSTM finish (gates in ep_x + biases; writes c,h,h_hi,h_lo)
template <int EPI>
__global__ __launch_bounds__(256, 1) void mma_gemm_kernel(
    const __nv_bfloat16* __restrict__ Ahi, const __nv_bfloat16* __restrict__ Alo,
    const __nv_bfloat16* __restrict__ Bhi, const __nv_bfloat16* __restrict__ Blo,
    const float* __restrict__ ep_x, const float* __restrict__ ep_W,
    const float* __restrict__ ep_b1, const float* __restrict__ ep_b2,
    float* __restrict__ out_c, float* __restrict__ out_h,
    __nv_bfloat16* __restrict__ out_hi, __nv_bfloat16* __restrict__ out_lo,
    float* __restrict__ out_enc, int xstride)
{
    extern __shared__ char dsm[];
    const int tid = threadIdx.x;
    const int wid = tid >> 5, lane = tid & 31;
    const int wm0 = (wid & 3) * 32;        // warp m-offset in tile
    const int wn0 = (wid >> 2) * 64;       // warp n-offset in tile
    const int bblock = blockIdx.x * 128;
    const int nblock = blockIdx.y * 128;
    const uint32_t sb = smem_u32(dsm);

    float acc[2][8][4];
#pragma unroll
    for (int i = 0; i < 2; i++)
#pragma unroll
        for (int q = 0; q < 8; q++)
#pragma unroll
            for (int v = 0; v < 4; v++) acc[i][q][v] = 0.0f;

    // row stride: 512 bf16 = 64 uint4
    const uint4* a_hi4 = (const uint4*)Ahi + (size_t)bblock * 64;
    const uint4* a_lo4 = (const uint4*)Alo + (size_t)bblock * 64;
    const uint4* b_hi4 = (const uint4*)Bhi + (size_t)nblock * 64;
    const uint4* b_lo4 = (const uint4*)Blo + (size_t)nblock * 64;

    uint4 va[4], vb[4];

#define LOADR(t) do {                                                           \
        const int term = (t) >> 3;                                              \
        const int k0u = ((t) & 7) * 8;                                          \
        const uint4* ap = (term == 2) ? a_lo4 : a_hi4;                          \
        const uint4* bp = (term == 1) ? b_lo4 : b_hi4;                          \
        _Pragma("unroll")                                                       \
        for (int i = 0; i < 4; i++) {                                           \
            int idx = tid + i * 256;                                            \
            int r = idx >> 3, u = idx & 7;                                      \
            size_t so = (size_t)r * 64 + k0u + u;                               \
            va[i] = __ldg(&ap[so]);                                             \
            vb[i] = __ldg(&bp[so]);                                             \
        }                                                                       \
    } while (0)

#define STOREB(buf) do {                                                        \
        const uint32_t ab = sb + (buf) * TILE_B;                                \
        const uint32_t bb = sb + 2 * TILE_B + (buf) * TILE_B;                   \
        _Pragma("unroll")                                                       \
        for (int i = 0; i < 4; i++) {                                           \
            int idx = tid + i * 256;                                            \
            int r = idx >> 3, u = idx & 7;                                      \
            uint32_t sw = r * 128 + ((u ^ (r & 7)) << 4);                       \
            sts128(ab + sw, va[i]);                                             \
            sts128(bb + sw, vb[i]);                                             \
        }                                                                       \
    } while (0)

    LOADR(0);
    STOREB(0);
    __syncthreads();

    // ldmatrix per-lane row components (fixed per lane)
    const int mat = lane >> 3;
    const int rofs = ((mat & 1) << 3) + (lane & 7);
    const int uofs = mat >> 1;

    for (int t = 0; t < NCHUNK; t++) {
        const int cur = t & 1;
        if (t + 1 < NCHUNK) LOADR(t + 1);

        const uint32_t abase = sb + cur * TILE_B;
        const uint32_t bbase = sb + 2 * TILE_B + cur * TILE_B;
#pragma unroll
        for (int s = 0; s < 4; s++) {
            const int u = 2 * s + uofs;
            uint32_t afr[2][4];
#pragma unroll
            for (int hm = 0; hm < 2; hm++) {
                const int row = wm0 + hm * 16 + rofs;
                ldm4(afr[hm][0], afr[hm][1], afr[hm][2], afr[hm][3],
                     abase + row * 128 + ((u ^ (row & 7)) << 4));
            }
            uint32_t bfr[8][2];
#pragma unroll
            for (int hn = 0; hn < 4; hn++) {
                const int row = wn0 + hn * 16 + rofs;
                uint32_t q0, q1, q2, q3;
                ldm4(q0, q1, q2, q3, bbase + row * 128 + ((u ^ (row & 7)) << 4));
                bfr[2 * hn][0] = q0; bfr[2 * hn][1] = q2;
                bfr[2 * hn + 1][0] = q1; bfr[2 * hn + 1][1] = q3;
            }
#pragma unroll
            for (int hm = 0; hm < 2; hm++)
#pragma unroll
                for (int q = 0; q < 8; q++)
                    mma16816(acc[hm][q], afr[hm][0], afr[hm][1], afr[hm][2], afr[hm][3],
                             bfr[q][0], bfr[q][1]);
        }
        if (t + 1 < NCHUNK) STOREB(cur ^ 1);
        __syncthreads();
    }

    // ---------------- stage accum to smem (reuse buffers) ----------------
    float* Cs = (float*)dsm;              // [128][130]
#pragma unroll
    for (int hm = 0; hm < 2; hm++) {
        const int mlo = wm0 + hm * 16 + (lane >> 2);
#pragma unroll
        for (int q = 0; q < 8; q++) {
            const int nc = wn0 + 8 * q + 2 * (lane & 3);
            *(float2*)&Cs[(size_t)mlo * 130 + nc] = make_float2(acc[hm][q][0], acc[hm][q][1]);
            *(float2*)&Cs[(size_t)(mlo + 8) * 130 + nc] = make_float2(acc[hm][q][2], acc[hm][q][3]);
        }
    }
    __syncthreads();

    // ---------------- epilogue: thread t -> row m=t>>1, half (t&1) --------
    const int m = bblock + (tid >> 1);
    const float* Crow = Cs + (size_t)(tid >> 1) * 130 + (tid & 1) * 64;

    if (EPI == 0 || EPI == 3) {
        float xv0 = 0.f, xv1 = 0.f, xv2 = 0.f, xv3 = 0.f;
        if (EPI == 0) {
            const float* xp = ep_x + (size_t)m * xstride;
            xv0 = xp[0]; xv1 = xp[1]; xv2 = xp[2]; xv3 = xp[3];
        }
        const int jbase = blockIdx.y * 32 + (tid & 1) * 16;
#pragma unroll
        for (int jj = 0; jj < 16; jj++) {
            const int jg = jbase + jj;
            float gi = Crow[4 * jj + 0];
            float gf = Crow[4 * jj + 1];
            float gg = Crow[4 * jj + 2];
            float go = Crow[4 * jj + 3];
            if (EPI == 0) {
                const float* w0 = ep_W + (size_t)(0 * HID + jg) * 4;
                const float* w1 = ep_W + (size_t)(1 * HID + jg) * 4;
                const float* w2 = ep_W + (size_t)(2 * HID + jg) * 4;
                const float* w3 = ep_W + (size_t)(3 * HID + jg) * 4;
                gi += xv0 * w0[0] + xv1 * w0[1] + xv2 * w0[2] + xv3 * w0[3];
                gf += xv0 * w1[0] + xv1 * w1[1] + xv2 * w1[2] + xv3 * w1[3];
                gg += xv0 * w2[0] + xv1 * w2[1] + xv2 * w2[2] + xv3 * w2[3];
                go += xv0 * w3[0] + xv1 * w3[1] + xv2 * w3[2] + xv3 * w3[3];
            } else {
                const float* gp = ep_x + (size_t)m * (4 * HID) + jg;
                gi += gp[0]; gf += gp[HID]; gg += gp[2 * HID]; go += gp[3 * HID];
            }
            gi += ep_b1[jg]            + ep_b2[jg];
            gf += ep_b1[HID + jg]      + ep_b2[HID + jg];
            gg += ep_b1[2 * HID + jg]  + ep_b2[2 * HID + jg];
            go += ep_b1[3 * HID + jg]  + ep_b2[3 * HID + jg];
            const size_t o = (size_t)m * HID + jg;
            const float cn = sigf(gf) * out_c[o] + sigf(gi) * tanhf(gg);
            const float hn = sigf(go) * tanhf(cn);
            out_c[o] = cn;
            out_h[o] = hn;
            __nv_bfloat16 hh, hl;
            bf_split(hn, hh, hl);
            out_hi[o] = hh; out_lo[o] = hl;
            if (EPI == 0) out_enc[(size_t)m * (SEQL * HID) + jg] = hn;
        }
    } else if (EPI == 1) {
        const int jbase = blockIdx.y * 32 + (tid & 1) * 16;
#pragma unroll
        for (int jj = 0; jj < 16; jj++) {
            const int jg = jbase + jj;
            float* gp = out_c + (size_t)m * (4 * HID) + jg;
            gp[0]       = Crow[4 * jj + 0];
            gp[HID]     = Crow[4 * jj + 1];
            gp[2 * HID] = Crow[4 * jj + 2];
            gp[3 * HID] = Crow[4 * jj + 3];
        }
    } else {  // EPI == 2: comb
        const float* xp = ep_x + (size_t)m * DIM;
        const float xv0 = xp[0], xv1 = xp[1], xv2 = xp[2], xv3 = xp[3];
        const int nb = nblock + (tid & 1) * 64;
#pragma unroll
        for (int c = 0; c < 64; c++) {
            const int j = nb + c;
            const float* w = ep_W + (size_t)j * (HID + DIM);
            float v = Crow[c] + ep_b1[j] +
                      xv0 * w[0] + xv1 * w[1] + xv2 * w[2] + xv3 * w[3];
            v = fmaxf(v, 0.0f);
            const size_t o = (size_t)m * HID + j;
            __nv_bfloat16 hh, hl;
            bf_split(v, hh, hl);
            out_hi[o] = hh; out_lo[o] = hl;
        }
    }
#undef LOADR
#undef STOREB
}

// ---------------- attention (SIMT; writes bf16 split) -----------------------
// h_r scramble: h_r[b][j] = h[2j + (b>>9)][b & 511]  (B = 2H)
__global__ void attn_kernel(const float* __restrict__ x, const float* __restrict__ h,
                            const float* __restrict__ attn_W, const float* __restrict__ attn_b,
                            const float* __restrict__ enc,
                            __nv_bfloat16* __restrict__ out_hi, __nv_bfloat16* __restrict__ out_lo) {
    __shared__ float hr[HID];
    __shared__ float w[SEQL];
    __shared__ float red[2];

    const int b = blockIdx.x;
    const int tid = threadIdx.x;
    const int bo = b >> 9;
    const int bc = b & (HID - 1);

    for (int j = tid; j < HID; j += 256)
        hr[j] = h[(size_t)(2 * j + bo) * HID + bc];
    __syncthreads();

    const int wid = tid >> 5, lane = tid & 31;
    for (int l = wid; l < SEQL; l += 8) {
        const float* wr = attn_W + (size_t)l * (HID + DIM);
        float s = 0.0f;
        for (int j = lane; j < HID; j += 32) s += hr[j] * wr[DIM + j];
#pragma unroll
        for (int off = 16; off; off >>= 1) s += __shfl_xor_sync(0xffffffffu, s, off);
        if (lane == 0) {
            s += attn_b[l] + x[b * DIM + 0] * wr[0] + x[b * DIM + 1] * wr[1] +
                 x[b * DIM + 2] * wr[2] + x[b * DIM + 3] * wr[3];
            w[l] = s;
        }
    }
    __syncthreads();
    if (tid == 0) {
        float m = w[0];
        for (int l = 1; l < SEQL; l++) m = fmaxf(m, w[l]);
        red[0] = m;
    }
    __syncthreads();
    if (tid < SEQL) w[tid] = expf(w[tid] - red[0]);
    __syncthreads();
    if (tid == 0) {
        float s = 0.0f;
        for (int l = 0; l < SEQL; l++) s += w[l];
        red[1] = 1.0f / s;
    }
    __syncthreads();
    if (tid < SEQL) w[tid] *= red[1];
    __syncthreads();

    for (int hc = tid; hc < HID; hc += 256) {
        const float* e = enc + (size_t)b * SEQL * HID + hc;
        float acc = 0.0f;
#pragma unroll
        for (int l = 0; l < SEQL; l++) acc += w[l] * e[(size_t)l * HID];
        __nv_bfloat16 hh, hl;
        bf_split(acc, hh, hl);
        const size_t o = (size_t)b * HID + hc;
        out_hi[o] = hh; out_lo[o] = hl;
    }
}

// ---------------- pred: h @ out_W^T + out_b; writes output + next x --------
__global__ void pred_kernel(const float* __restrict__ h, const float* __restrict__ out_W,
                            const float* __restrict__ out_b, float* __restrict__ x_next,
                            float* __restrict__ out, int t) {
    const int wid = threadIdx.x >> 5, lane = threadIdx.x & 31;
    const int b = blockIdx.x * 8 + wid;
    float a0 = 0.f, a1 = 0.f, a2 = 0.f, a3 = 0.f;
    for (int j = lane; j < HID; j += 32) {
        float hv = h[(size_t)b * HID + j];
        a0 += hv * out_W[0 * HID + j];
        a1 += hv * out_W[1 * HID + j];
        a2 += hv * out_W[2 * HID + j];
        a3 += hv * out_W[3 * HID + j];
    }
#pragma unroll
    for (int off = 16; off; off >>= 1) {
        a0 += __shfl_xor_sync(0xffffffffu, a0, off);
        a1 += __shfl_xor_sync(0xffffffffu, a1, off);
        a2 += __shfl_xor_sync(0xffffffffu, a2, off);
        a3 += __shfl_xor_sync(0xffffffffu, a3, off);
    }
    if (lane == 0) {
        float v0 = a0 + out_b[0], v1 = a1 + out_b[1], v2 = a2 + out_b[2], v3 = a3 + out_b[3];
        size_t o = ((size_t)b * TLEN + t) * DIM;
        out[o + 0] = v0; out[o + 1] = v1; out[o + 2] = v2; out[o + 3] = v3;
        x_next[b * DIM + 0] = v0; x_next[b * DIM + 1] = v1;
        x_next[b * DIM + 2] = v2; x_next[b * DIM + 3] = v3;
    }
}

// ---------------- host -----------------------------------------------------
extern "C" void kernel_launch(void* const* d_in, const int* in_sizes, int n_in,
                              void* d_out, int out_size) {
    int base = 1;
    if (n_in >= 16 && in_sizes[1] == 1) base = 2;  // skip target_len scalar

    const float* input    = (const float*)d_in[0];
    const float* enc_W_ih = (const float*)d_in[base + 0];
    const float* enc_W_hh = (const float*)d_in[base + 1];
    const float* enc_b_ih = (const float*)d_in[base + 2];
    const float* enc_b_hh = (const float*)d_in[base + 3];
    const float* attn_W   = (const float*)d_in[base + 4];
    const float* attn_b   = (const float*)d_in[base + 5];
    const float* comb_W   = (const float*)d_in[base + 6];
    const float* comb_b   = (const float*)d_in[base + 7];
    const float* dec_W_ih = (const float*)d_in[base + 8];
    const float* dec_W_hh = (const float*)d_in[base + 9];
    const float* dec_b_ih = (const float*)d_in[base + 10];
    const float* dec_b_hh = (const float*)d_in[base + 11];
    const float* out_W    = (const float*)d_in[base + 12];
    const float* out_b    = (const float*)d_in[base + 13];
    float* out = (float*)d_out;

    float *enc_p, *h_p, *c_p, *x_p, *gates_p;
    __nv_bfloat16 *hsh_p, *hsl_p, *ath_p, *atl_p, *cbh_p, *cbl_p;
    __nv_bfloat16 *wehh_h, *wehh_l, *wdhh_h, *wdhh_l, *wdih_h, *wdih_l, *wcmb_h, *wcmb_l;
    cudaGetSymbolAddress((void**)&enc_p, g_enc);
    cudaGetSymbolAddress((void**)&h_p, g_h);
    cudaGetSymbolAddress((void**)&c_p, g_c);
    cudaGetSymbolAddress((void**)&x_p, g_x);
    cudaGetSymbolAddress((void**)&gates_p, g_gates);
    cudaGetSymbolAddress((void**)&hsh_p, g_hs_hi);
    cudaGetSymbolAddress((void**)&hsl_p, g_hs_lo);
    cudaGetSymbolAddress((void**)&ath_p, g_attn_hi);
    cudaGetSymbolAddress((void**)&atl_p, g_attn_lo);
    cudaGetSymbolAddress((void**)&cbh_p, g_comb_hi);
    cudaGetSymbolAddress((void**)&cbl_p, g_comb_lo);
    cudaGetSymbolAddress((void**)&wehh_h, g_wehh_hi);
    cudaGetSymbolAddress((void**)&wehh_l, g_wehh_lo);
    cudaGetSymbolAddress((void**)&wdhh_h, g_wdhh_hi);
    cudaGetSymbolAddress((void**)&wdhh_l, g_wdhh_lo);
    cudaGetSymbolAddress((void**)&wdih_h, g_wdih_hi);
    cudaGetSymbolAddress((void**)&wdih_l, g_wdih_lo);
    cudaGetSymbolAddress((void**)&wcmb_h, g_wcmb_hi);
    cudaGetSymbolAddress((void**)&wcmb_l, g_wcmb_lo);

    cudaFuncSetAttribute(mma_gemm_kernel<0>, cudaFuncAttributeMaxDynamicSharedMemorySize, DSMEM_B);
    cudaFuncSetAttribute(mma_gemm_kernel<1>, cudaFuncAttributeMaxDynamicSharedMemorySize, DSMEM_B);
    cudaFuncSetAttribute(mma_gemm_kernel<2>, cudaFuncAttributeMaxDynamicSharedMemorySize, DSMEM_B);
    cudaFuncSetAttribute(mma_gemm_kernel<3>, cudaFuncAttributeMaxDynamicSharedMemorySize, DSMEM_B);

    // prep: split/interleave weights
    split_gate_w<<<(4 * HID * HID + 255) / 256, 256>>>(enc_W_hh, wehh_h, wehh_l);
    split_gate_w<<<(4 * HID * HID + 255) / 256, 256>>>(dec_W_hh, wdhh_h, wdhh_l);
    split_gate_w<<<(4 * HID * HID + 255) / 256, 256>>>(dec_W_ih, wdih_h, wdih_l);
    split_comb_w<<<(HID * HID + 255) / 256, 256>>>(comb_W, wcmb_h, wcmb_l);
    init_kernel<<<(HS + 255) / 256, 256>>>(input, c_p, hsh_p, hsl_p, x_p);

    const dim3 full_grid(BATCH / 128, (4 * HID) / 128);  // (8, 16)
    const dim3 comb_grid(BATCH / 128, HID / 128);        // (8, 4)

    int cur = 0;
    // encoder: 50 sequential tensor-core LSTM steps
    for (int t = 0; t < SEQL; t++) {
        mma_gemm_kernel<0><<<full_grid, 256, DSMEM_B>>>(
            hsh_p + (size_t)cur * HS, hsl_p + (size_t)cur * HS, wehh_h, wehh_l,
            input + (size_t)t * DIM, enc_W_ih, enc_b_ih, enc_b_hh,
            c_p, h_p, hsh_p + (size_t)(cur ^ 1) * HS, hsl_p + (size_t)(cur ^ 1) * HS,
            enc_p + (size_t)t * HID, SEQL * DIM);
        cur ^= 1;
    }
    // decoder: 30 sequential steps
    for (int s = 0; s < TLEN; s++) {
        mma_gemm_kernel<1><<<full_grid, 256, DSMEM_B>>>(
            hsh_p + (size_t)cur * HS, hsl_p + (size_t)cur * HS, wdhh_h, wdhh_l,
            nullptr, nullptr, nullptr, nullptr,
            gates_p, nullptr, nullptr, nullptr, nullptr, 0);
        attn_kernel<<<BATCH, 256>>>(x_p, h_p, attn_W, attn_b, enc_p, ath_p, atl_p);
        mma_gemm_kernel<2><<<comb_grid, 256, DSMEM_B>>>(
            ath_p, atl_p, wcmb_h, wcmb_l,
            x_p, comb_W, comb_b, nullptr,
            nullptr, nullptr, cbh_p, cbl_p, nullptr, 0);
        mma_gemm_kernel<3><<<full_grid, 256, DSMEM_B>>>(
            cbh_p, cbl_p, wdih_h, wdih_l,
            gates_p, nullptr, dec_b_ih, dec_b_hh,
            c_p, h_p, hsh_p + (size_t)(cur ^ 1) * HS, hsl_p + (size_t)(cur ^ 1) * HS,
            nullptr, 0);
        pred_kernel<<<BATCH / 8, 256>>>(h_p, out_W, out_b, x_p, out, s);
        cur ^= 1;
    }
}